// round 13
// baseline (speedup 1.0000x reference)
#include <cuda_runtime.h>
#include <cuda_bf16.h>
#include <math.h>
#include <stdint.h>

#define BB 32
#define NN 1024
#define FF 128
#define RPB 8
#define NBLK (NN / RPB)     // 128 partial slabs per b
#define GC 32
#define CK 32

// State: E = exp(y) in [1, e], uint16 fixed-point: 64MB
__device__ unsigned short g_Q[BB * NN * NN];
__device__ float g_colsum[BB * NN];
__device__ float g_part[NBLK * BB * NN];          // 16MB colsum partials
__device__ __nv_bfloat16 g_Eh[BB * NN * NN];      // 64MB final E hi
__device__ __nv_bfloat16 g_El[BB * NN * NN];      // 64MB final E lo
__device__ __nv_bfloat16 g_B[BB * NN * 256];      // 16MB scaled feature [hi|lo]
__device__ int g_ctr[BB];                         // tail-reduce election (0-init; reset each use)

// ---------------- fixed-point (magic-number, no cvt pipe) ----------------
#define EMAXR 1.7182837f
#define K1C (EMAXR / 65535.0f)
#define C1C (1.0f - 8388608.0f * K1C)
#define K2C (65535.0f / EMAXR)
#define C2C (8388608.0f - K2C)

__device__ __forceinline__ float decE(uint32_t u16) {
    return fmaf(__uint_as_float(0x4B000000u | u16), K1C, C1C);
}
__device__ __forceinline__ uint32_t enc2(float a, float b) {
    uint32_t ba = __float_as_uint(fmaf(a, K2C, C2C));
    uint32_t bb = __float_as_uint(fmaf(b, K2C, C2C));
    return (ba & 0xFFFFu) | (bb << 16);
}

// ---------------- last-block tail reduction: partials -> g_colsum ----------
// Deterministic: exactly one block per b performs a fixed-order sum.
__device__ __forceinline__ void tail_reduce(int b, int t) {
    __threadfence();
    __shared__ int lastS;
    if (t == 0) lastS = (atomicAdd(&g_ctr[b], 1) == NBLK - 1) ? 1 : 0;
    __syncthreads();
    if (!lastS) return;
    __threadfence();                       // acquire: see all slabs
    if (t == 0) g_ctr[b] = 0;              // reset for next launch / replay
    const float4* P = (const float4*)g_part;
    float4 a0 = make_float4(0.f, 0.f, 0.f, 0.f);
    float4 a1 = a0, a2 = a0, a3 = a0;
#pragma unroll 4
    for (int p = 0; p < NBLK; p += 4) {
        float4 v0 = P[((size_t)(p + 0) * BB + b) * 256 + t];
        float4 v1 = P[((size_t)(p + 1) * BB + b) * 256 + t];
        float4 v2 = P[((size_t)(p + 2) * BB + b) * 256 + t];
        float4 v3 = P[((size_t)(p + 3) * BB + b) * 256 + t];
        a0.x += v0.x; a0.y += v0.y; a0.z += v0.z; a0.w += v0.w;
        a1.x += v1.x; a1.y += v1.y; a1.z += v1.z; a1.w += v1.w;
        a2.x += v2.x; a2.y += v2.y; a2.z += v2.z; a2.w += v2.w;
        a3.x += v3.x; a3.y += v3.y; a3.z += v3.z; a3.w += v3.w;
    }
    float4 r;
    r.x = (a0.x + a1.x) + (a2.x + a3.x);
    r.y = (a0.y + a1.y) + (a2.y + a3.y);
    r.z = (a0.z + a1.z) + (a2.z + a3.z);
    r.w = (a0.w + a1.w) + (a2.w + a3.w);
    *(float4*)&g_colsum[b * NN + t * 4] = r;
}

// ---------------- PTX helpers ----------------
__device__ __forceinline__ uint32_t smem_u32(const void* p) {
    uint32_t a;
    asm("{ .reg .u64 t; cvta.to.shared.u64 t, %1; cvt.u32.u64 %0, t; }" : "=r"(a) : "l"(p));
    return a;
}
#define CP16(dst, src) asm volatile("cp.async.cg.shared.global [%0], [%1], 16;" :: "r"(dst), "l"(src))
#define CP_COMMIT()    asm volatile("cp.async.commit_group;" ::: "memory")
#define CP_WAIT1()     asm volatile("cp.async.wait_group 1;" ::: "memory")
#define CP_WAIT0()     asm volatile("cp.async.wait_group 0;" ::: "memory")

__device__ __forceinline__ void ldsm_x4(uint32_t* r, uint32_t addr) {
    asm volatile("ldmatrix.sync.aligned.m8n8.x4.shared.b16 {%0,%1,%2,%3}, [%4];"
                 : "=r"(r[0]), "=r"(r[1]), "=r"(r[2]), "=r"(r[3]) : "r"(addr));
}
__device__ __forceinline__ void ldsm_x4_t(uint32_t* r, uint32_t addr) {
    asm volatile("ldmatrix.sync.aligned.m8n8.x4.trans.shared.b16 {%0,%1,%2,%3}, [%4];"
                 : "=r"(r[0]), "=r"(r[1]), "=r"(r[2]), "=r"(r[3]) : "r"(addr));
}
__device__ __forceinline__ void mma_bf16(float* d, const uint32_t* a, const uint32_t* b) {
    asm volatile("mma.sync.aligned.m16n8k16.row.col.f32.bf16.bf16.f32 "
                 "{%0,%1,%2,%3}, {%4,%5,%6,%7}, {%8,%9}, {%0,%1,%2,%3};"
                 : "+f"(d[0]), "+f"(d[1]), "+f"(d[2]), "+f"(d[3])
                 : "r"(a[0]), "r"(a[1]), "r"(a[2]), "r"(a[3]), "r"(b[0]), "r"(b[1]));
}

union PackB4 { __nv_bfloat16 h[4]; uint2 u; };

// ===========================================================================
// Init: row softmax #1; store enc(E1) + partials; tail-reduce colsum.
// ===========================================================================
__global__ __launch_bounds__(256, 4) void k_init(const float* __restrict__ tmpl,
                                                 const float* __restrict__ uni) {
    const int b = blockIdx.y, r0 = blockIdx.x * RPB, t = threadIdx.x;
    const int j0 = t * 4;
    __shared__ float part[RPB][256];
    __shared__ float rred[RPB];

    float4 x4[RPB];
#pragma unroll
    for (int rr = 0; rr < RPB; rr++) {
        const int row = r0 + rr;
        float4 u = *(const float4*)&uni[((size_t)b * NN + row) * NN + j0];
        float4 tm = *(const float4*)&tmpl[(size_t)row * NN + j0];
        float4 x;
        x.x = (tm.x - __logf(-logf(u.x + 1e-12f) + 1e-12f)) * 5.0f;
        x.y = (tm.y - __logf(-logf(u.y + 1e-12f) + 1e-12f)) * 5.0f;
        x.z = (tm.z - __logf(-logf(u.z + 1e-12f) + 1e-12f)) * 5.0f;
        x.w = (tm.w - __logf(-logf(u.w + 1e-12f) + 1e-12f)) * 5.0f;
        x4[rr] = x;
        part[rr][t] = fmaxf(fmaxf(x.x, x.y), fmaxf(x.z, x.w));
    }
    __syncthreads();
    {
        const int w = t >> 5, lane = t & 31;
        float v = part[w][lane];
#pragma unroll
        for (int k = 1; k < 8; k++) v = fmaxf(v, part[w][lane + k * 32]);
#pragma unroll
        for (int o = 16; o > 0; o >>= 1) v = fmaxf(v, __shfl_xor_sync(0xffffffffu, v, o));
        if (lane == 0) rred[w] = v;
    }
    __syncthreads();
#pragma unroll
    for (int rr = 0; rr < RPB; rr++) {
        const float mx = rred[rr];
        float4 e;
        e.x = __expf(x4[rr].x - mx);
        e.y = __expf(x4[rr].y - mx);
        e.z = __expf(x4[rr].z - mx);
        e.w = __expf(x4[rr].w - mx);
        x4[rr] = e;
        part[rr][t] = (e.x + e.y) + (e.z + e.w);
    }
    __syncthreads();
    {
        const int w = t >> 5, lane = t & 31;
        float v = part[w][lane];
#pragma unroll
        for (int k = 1; k < 8; k++) v += part[w][lane + k * 32];
#pragma unroll
        for (int o = 16; o > 0; o >>= 1) v += __shfl_xor_sync(0xffffffffu, v, o);
        if (lane == 0) rred[w] = 1.0f / v;
    }
    __syncthreads();
    float4 cs = make_float4(0.f, 0.f, 0.f, 0.f);
#pragma unroll
    for (int rr = 0; rr < RPB; rr++) {
        const float inv = rred[rr];
        float Ex = __expf(x4[rr].x * inv);
        float Ey = __expf(x4[rr].y * inv);
        float Ez = __expf(x4[rr].z * inv);
        float Ew = __expf(x4[rr].w * inv);
        uint2 o;
        o.x = enc2(Ex, Ey);
        o.y = enc2(Ez, Ew);
        *(uint2*)&g_Q[((size_t)b * NN + r0 + rr) * NN + j0] = o;
        cs.x += Ex; cs.y += Ey; cs.z += Ez; cs.w += Ew;
    }
    *(float4*)&g_part[((size_t)blockIdx.x * BB + b) * NN + j0] = cs;
    tail_reduce(b, t);
}

// ===========================================================================
// Fused pair (col+row softmax) on u16 state; tail-reduce colsum.
// ===========================================================================
__global__ __launch_bounds__(256, 4) void k_fused() {
    const int b = blockIdx.y, r0 = blockIdx.x * RPB, t = threadIdx.x;
    const int j0 = t * 4;
    __shared__ float part[RPB][256];
    __shared__ float rinv[RPB];

    float4 cv = *(const float4*)&g_colsum[b * NN + j0];
    const float4 ic = make_float4(1.0f / cv.x, 1.0f / cv.y, 1.0f / cv.z, 1.0f / cv.w);

    float4 r4[RPB];
#pragma unroll
    for (int rr = 0; rr < RPB; rr++) {
        uint2 w = *(const uint2*)&g_Q[((size_t)b * NN + r0 + rr) * NN + j0];
        float4 r;
        r.x = __expf(decE(w.x & 0xFFFFu) * ic.x);
        r.y = __expf(decE(w.x >> 16) * ic.y);
        r.z = __expf(decE(w.y & 0xFFFFu) * ic.z);
        r.w = __expf(decE(w.y >> 16) * ic.w);
        r4[rr] = r;
        part[rr][t] = (r.x + r.y) + (r.z + r.w);
    }
    __syncthreads();
    {
        const int w = t >> 5, lane = t & 31;
        float v = part[w][lane];
#pragma unroll
        for (int k = 1; k < 8; k++) v += part[w][lane + k * 32];
#pragma unroll
        for (int o = 16; o > 0; o >>= 1) v += __shfl_xor_sync(0xffffffffu, v, o);
        if (lane == 0) rinv[w] = 1.0f / v;
    }
    __syncthreads();
    float4 cs = make_float4(0.f, 0.f, 0.f, 0.f);
#pragma unroll
    for (int rr = 0; rr < RPB; rr++) {
        const float ir = rinv[rr];
        float Ex = __expf(r4[rr].x * ir);
        float Ey = __expf(r4[rr].y * ir);
        float Ez = __expf(r4[rr].z * ir);
        float Ew = __expf(r4[rr].w * ir);
        uint2 o;
        o.x = enc2(Ex, Ey);
        o.y = enc2(Ez, Ew);
        *(uint2*)&g_Q[((size_t)b * NN + r0 + rr) * NN + j0] = o;
        cs.x += Ex; cs.y += Ey; cs.z += Ez; cs.w += Ew;
    }
    *(float4*)&g_part[((size_t)blockIdx.x * BB + b) * NN + j0] = cs;
    tail_reduce(b, t);
}

// Last pair: col#9 + row#10; store E10 as bf16 hi/lo; tail-reduce colsum.
__global__ __launch_bounds__(256, 4) void k_fused_last() {
    const int b = blockIdx.y, r0 = blockIdx.x * RPB, t = threadIdx.x;
    const int j0 = t * 4;
    __shared__ float part[RPB][256];
    __shared__ float rinv[RPB];

    float4 cv = *(const float4*)&g_colsum[b * NN + j0];
    const float4 ic = make_float4(1.0f / cv.x, 1.0f / cv.y, 1.0f / cv.z, 1.0f / cv.w);

    float4 r4[RPB];
#pragma unroll
    for (int rr = 0; rr < RPB; rr++) {
        uint2 w = *(const uint2*)&g_Q[((size_t)b * NN + r0 + rr) * NN + j0];
        float4 r;
        r.x = __expf(decE(w.x & 0xFFFFu) * ic.x);
        r.y = __expf(decE(w.x >> 16) * ic.y);
        r.z = __expf(decE(w.y & 0xFFFFu) * ic.z);
        r.w = __expf(decE(w.y >> 16) * ic.w);
        r4[rr] = r;
        part[rr][t] = (r.x + r.y) + (r.z + r.w);
    }
    __syncthreads();
    {
        const int w = t >> 5, lane = t & 31;
        float v = part[w][lane];
#pragma unroll
        for (int k = 1; k < 8; k++) v += part[w][lane + k * 32];
#pragma unroll
        for (int o = 16; o > 0; o >>= 1) v += __shfl_xor_sync(0xffffffffu, v, o);
        if (lane == 0) rinv[w] = 1.0f / v;
    }
    __syncthreads();
    float4 cs = make_float4(0.f, 0.f, 0.f, 0.f);
#pragma unroll
    for (int rr = 0; rr < RPB; rr++) {
        const float ir = rinv[rr];
        float Ex = __expf(r4[rr].x * ir);
        float Ey = __expf(r4[rr].y * ir);
        float Ez = __expf(r4[rr].z * ir);
        float Ew = __expf(r4[rr].w * ir);
        PackB4 H, L;
        H.h[0] = __float2bfloat16(Ex); L.h[0] = __float2bfloat16(Ex - __bfloat162float(H.h[0]));
        H.h[1] = __float2bfloat16(Ey); L.h[1] = __float2bfloat16(Ey - __bfloat162float(H.h[1]));
        H.h[2] = __float2bfloat16(Ez); L.h[2] = __float2bfloat16(Ez - __bfloat162float(H.h[2]));
        H.h[3] = __float2bfloat16(Ew); L.h[3] = __float2bfloat16(Ew - __bfloat162float(H.h[3]));
        const size_t idx = ((size_t)b * NN + r0 + rr) * NN + j0;
        *(uint2*)&g_Eh[idx] = H.u;
        *(uint2*)&g_El[idx] = L.u;
        cs.x += Ex; cs.y += Ey; cs.z += Ez; cs.w += Ew;
    }
    *(float4*)&g_part[((size_t)blockIdx.x * BB + b) * NN + j0] = cs;
    tail_reduce(b, t);
}

// ===========================================================================
// B precompute: reads g_colsum directly (tail-reduced by fused_last).
// grid (128, BB), 256 thr, 8 k-rows per block.
// ===========================================================================
__global__ __launch_bounds__(256) void k_prepB(const float* __restrict__ feat) {
    const int b = blockIdx.y, k = blockIdx.x * 8 + (threadIdx.x >> 5);
    const int f4 = (threadIdx.x & 31) * 4;
    const float ic = 1.0f / g_colsum[b * NN + k];
    float4 v = *(const float4*)&feat[((size_t)b * NN + k) * FF + f4];
    v.x *= ic; v.y *= ic; v.z *= ic; v.w *= ic;
    PackB4 H, L;
    H.h[0] = __float2bfloat16(v.x); L.h[0] = __float2bfloat16(v.x - __bfloat162float(H.h[0]));
    H.h[1] = __float2bfloat16(v.y); L.h[1] = __float2bfloat16(v.y - __bfloat162float(H.h[1]));
    H.h[2] = __float2bfloat16(v.z); L.h[2] = __float2bfloat16(v.z - __bfloat162float(H.h[2]));
    H.h[3] = __float2bfloat16(v.w); L.h[3] = __float2bfloat16(v.w - __bfloat162float(H.h[3]));
    const size_t rb = ((size_t)b * NN + k) * 256;
    *(uint2*)&g_B[rb + f4] = H.u;
    *(uint2*)&g_B[rb + 128 + f4] = L.u;
}

// ===========================================================================
// HMMA bf16 split GEMM (R11 passing version: Eh/El A, 3 products)
// ===========================================================================
#define ABUF 37888
#define AHI 0
#define ALO 10240
#define BHI 20480
#define BLO_OFF 8704

__global__ __launch_bounds__(256) void k_gemm(float* __restrict__ out) {
    extern __shared__ char smem[];
    const int b = blockIdx.y, i0 = blockIdx.x * 128, t = threadIdx.x;
    const int wid = t >> 5, lane = t & 31;
    const int wm = wid & 3, wn = wid >> 2;
    const uint32_t sb = smem_u32(smem);

    const int rowA = t >> 1, halfA = (t & 1) * 32;
    const int rowB = t >> 3, pB = (t & 7) * 64;
    const char* srcAh = (const char*)(g_Eh + ((size_t)b * NN + i0 + rowA) * NN) + halfA;
    const char* srcAl = (const char*)(g_El + ((size_t)b * NN + i0 + rowA) * NN) + halfA;
    const char* srcB  = (const char*)(g_B + (size_t)b * NN * 256) + rowB * 512 + pB;
    const uint32_t dAh = sb + AHI + rowA * 80 + halfA;
    const uint32_t dAl = sb + ALO + rowA * 80 + halfA;
    const uint32_t dB  = sb + BHI + (pB < 256 ? 0 : BLO_OFF) + rowB * 272 + (pB & 255);

#define ISSUE_CHUNK(cc)  do {                                            \
        const int _s = (cc) & 1;                                         \
        const size_t _ao = (size_t)(cc) * CK * 2;                        \
        CP16(dAh + _s * ABUF,      srcAh + _ao);                         \
        CP16(dAh + _s * ABUF + 16, srcAh + _ao + 16);                    \
        CP16(dAl + _s * ABUF,      srcAl + _ao);                         \
        CP16(dAl + _s * ABUF + 16, srcAl + _ao + 16);                    \
        const size_t _bo = (size_t)(cc) * CK * 512;                      \
        CP16(dB + _s * ABUF,      srcB + _bo);                           \
        CP16(dB + _s * ABUF + 16, srcB + _bo + 16);                      \
        CP16(dB + _s * ABUF + 32, srcB + _bo + 32);                      \
        CP16(dB + _s * ABUF + 48, srcB + _bo + 48);                      \
        CP_COMMIT();                                                     \
    } while (0)

    float acc[2][8][4];
#pragma unroll
    for (int mf = 0; mf < 2; mf++)
#pragma unroll
        for (int nf = 0; nf < 8; nf++)
#pragma unroll
            for (int q = 0; q < 4; q++) acc[mf][nf][q] = 0.f;

    ISSUE_CHUNK(0);

    for (int c = 0; c < GC; ++c) {
        if (c < GC - 1) { ISSUE_CHUNK(c + 1); CP_WAIT1(); }
        else            { CP_WAIT0(); }
        __syncthreads();

        const uint32_t bufA = sb + (c & 1) * ABUF;
#pragma unroll
        for (int ks = 0; ks < 2; ks++) {
            uint32_t aH[2][4], aL[2][4];
#pragma unroll
            for (int mf = 0; mf < 2; mf++) {
                const int r0 = wm * 32 + mf * 16;
                const uint32_t ad = bufA + AHI + (r0 + (lane & 15)) * 80 + ks * 32 + (lane >> 4) * 16;
                ldsm_x4(aH[mf], ad);
                ldsm_x4(aL[mf], ad + (ALO - AHI));
            }
            uint32_t bH[4][4], bL[4][4];
#pragma unroll
            for (int ng = 0; ng < 4; ng++) {
                const int n0 = wn * 64 + ng * 16;
                const uint32_t bd = bufA + BHI + (ks * 16 + (lane & 15)) * 272 + n0 * 2 + (lane >> 4) * 16;
                ldsm_x4_t(bH[ng], bd);
                ldsm_x4_t(bL[ng], bd + BLO_OFF);
            }
#pragma unroll
            for (int mf = 0; mf < 2; mf++)
#pragma unroll
                for (int ng = 0; ng < 4; ng++)
#pragma unroll
                    for (int h = 0; h < 2; h++) {
                        float* d = acc[mf][ng * 2 + h];
                        mma_bf16(d, aH[mf], &bH[ng][h * 2]);
                        mma_bf16(d, aH[mf], &bL[ng][h * 2]);
                        mma_bf16(d, aL[mf], &bH[ng][h * 2]);
                    }
        }
        __syncthreads();
    }

    const int gid = lane >> 2, t4 = lane & 3;
#pragma unroll
    for (int mf = 0; mf < 2; mf++) {
        const int row = i0 + wm * 32 + mf * 16 + gid;
#pragma unroll
        for (int nf = 0; nf < 8; nf++) {
            const int col = wn * 64 + nf * 8 + t4 * 2;
            const float* d = acc[mf][nf];
            *(float2*)&out[((size_t)b * NN + row) * FF + col]     = make_float2(d[0], d[1]);
            *(float2*)&out[((size_t)b * NN + row + 8) * FF + col] = make_float2(d[2], d[3]);
        }
    }
}

// ===========================================================================
extern "C" void kernel_launch(void* const* d_in, const int* in_sizes, int n_in,
                              void* d_out, int out_size) {
    const float* feat = (const float*)d_in[0];   // [B,N,F]
    const float* tmpl = (const float*)d_in[1];   // [1,N,N]
    const float* uni  = (const float*)d_in[2];   // [B,N,N]
    float* out = (float*)d_out;                  // [B,N,F]

    cudaFuncSetAttribute(k_gemm, cudaFuncAttributeMaxDynamicSharedMemorySize, 2 * ABUF);

    k_init<<<dim3(NBLK, BB), 256>>>(tmpl, uni);
    for (int it = 0; it < 8; ++it)
        k_fused<<<dim3(NBLK, BB), 256>>>();
    k_fused_last<<<dim3(NBLK, BB), 256>>>();
    k_prepB<<<dim3(NBLK, BB), 256>>>(feat);
    k_gemm<<<dim3(8, BB), 256, 2 * ABUF>>>(out);
}

// round 14
// speedup vs baseline: 1.5413x; 1.5413x over previous
#include <cuda_runtime.h>
#include <cuda_fp16.h>
#include <math.h>
#include <stdint.h>

#define BB 32
#define NN 1024
#define FF 128
#define RPB 8
#define NBLK (NN / RPB)
#define GC 32
#define CK 32

// State: E = exp(y) in [1, e], uint16 fixed-point: 64MB
__device__ unsigned short g_Q[BB * NN * NN];
__device__ float g_colsum[BB * NN];
__device__ float g_part[NBLK * BB * NN];          // 16MB colsum partials
__device__ __half g_F[BB * NN * NN];              // 64MB final E (fp16, GEMM A)
__device__ __half g_B[BB * NN * FF];              // 8MB scaled feature (fp16, GEMM B)

// ---------------- fixed-point (magic-number, no cvt pipe) ----------------
#define EMAXR 1.7182837f
#define K1C (EMAXR / 65535.0f)
#define C1C (1.0f - 8388608.0f * K1C)
#define K2C (65535.0f / EMAXR)
#define C2C (8388608.0f - K2C)

__device__ __forceinline__ float decE(uint32_t u16) {
    return fmaf(__uint_as_float(0x4B000000u | u16), K1C, C1C);
}
__device__ __forceinline__ uint32_t enc2(float a, float b) {
    uint32_t ba = __float_as_uint(fmaf(a, K2C, C2C));
    uint32_t bb = __float_as_uint(fmaf(b, K2C, C2C));
    return (ba & 0xFFFFu) | (bb << 16);
}

// ---------------- PTX helpers ----------------
__device__ __forceinline__ uint32_t smem_u32(const void* p) {
    uint32_t a;
    asm("{ .reg .u64 t; cvta.to.shared.u64 t, %1; cvt.u32.u64 %0, t; }" : "=r"(a) : "l"(p));
    return a;
}
#define CP16(dst, src) asm volatile("cp.async.cg.shared.global [%0], [%1], 16;" :: "r"(dst), "l"(src))
#define CP_COMMIT()    asm volatile("cp.async.commit_group;" ::: "memory")
#define CP_WAIT1()     asm volatile("cp.async.wait_group 1;" ::: "memory")
#define CP_WAIT0()     asm volatile("cp.async.wait_group 0;" ::: "memory")

__device__ __forceinline__ void ldsm_x4(uint32_t* r, uint32_t addr) {
    asm volatile("ldmatrix.sync.aligned.m8n8.x4.shared.b16 {%0,%1,%2,%3}, [%4];"
                 : "=r"(r[0]), "=r"(r[1]), "=r"(r[2]), "=r"(r[3]) : "r"(addr));
}
__device__ __forceinline__ void ldsm_x4_t(uint32_t* r, uint32_t addr) {
    asm volatile("ldmatrix.sync.aligned.m8n8.x4.trans.shared.b16 {%0,%1,%2,%3}, [%4];"
                 : "=r"(r[0]), "=r"(r[1]), "=r"(r[2]), "=r"(r[3]) : "r"(addr));
}
__device__ __forceinline__ void mma_f16(float* d, const uint32_t* a, const uint32_t* b) {
    asm volatile("mma.sync.aligned.m16n8k16.row.col.f32.f16.f16.f32 "
                 "{%0,%1,%2,%3}, {%4,%5,%6,%7}, {%8,%9}, {%0,%1,%2,%3};"
                 : "+f"(d[0]), "+f"(d[1]), "+f"(d[2]), "+f"(d[3])
                 : "r"(a[0]), "r"(a[1]), "r"(a[2]), "r"(a[3]), "r"(b[0]), "r"(b[1]));
}

union PackH4 { __half h[4]; uint2 u; };

// ===========================================================================
// Init: row softmax #1; store enc(E1) + colsum partials.
// ===========================================================================
__global__ __launch_bounds__(256, 4) void k_init(const float* __restrict__ tmpl,
                                                 const float* __restrict__ uni) {
    const int b = blockIdx.y, r0 = blockIdx.x * RPB, t = threadIdx.x;
    const int j0 = t * 4;
    __shared__ float part[RPB][256];
    __shared__ float rred[RPB];

    float4 x4[RPB];
#pragma unroll
    for (int rr = 0; rr < RPB; rr++) {
        const int row = r0 + rr;
        float4 u = *(const float4*)&uni[((size_t)b * NN + row) * NN + j0];
        float4 tm = *(const float4*)&tmpl[(size_t)row * NN + j0];
        float4 x;
        x.x = (tm.x - __logf(-logf(u.x + 1e-12f) + 1e-12f)) * 5.0f;
        x.y = (tm.y - __logf(-logf(u.y + 1e-12f) + 1e-12f)) * 5.0f;
        x.z = (tm.z - __logf(-logf(u.z + 1e-12f) + 1e-12f)) * 5.0f;
        x.w = (tm.w - __logf(-logf(u.w + 1e-12f) + 1e-12f)) * 5.0f;
        x4[rr] = x;
        part[rr][t] = fmaxf(fmaxf(x.x, x.y), fmaxf(x.z, x.w));
    }
    __syncthreads();
    {
        const int w = t >> 5, lane = t & 31;
        float v = part[w][lane];
#pragma unroll
        for (int k = 1; k < 8; k++) v = fmaxf(v, part[w][lane + k * 32]);
#pragma unroll
        for (int o = 16; o > 0; o >>= 1) v = fmaxf(v, __shfl_xor_sync(0xffffffffu, v, o));
        if (lane == 0) rred[w] = v;
    }
    __syncthreads();
#pragma unroll
    for (int rr = 0; rr < RPB; rr++) {
        const float mx = rred[rr];
        float4 e;
        e.x = __expf(x4[rr].x - mx);
        e.y = __expf(x4[rr].y - mx);
        e.z = __expf(x4[rr].z - mx);
        e.w = __expf(x4[rr].w - mx);
        x4[rr] = e;
        part[rr][t] = (e.x + e.y) + (e.z + e.w);
    }
    __syncthreads();
    {
        const int w = t >> 5, lane = t & 31;
        float v = part[w][lane];
#pragma unroll
        for (int k = 1; k < 8; k++) v += part[w][lane + k * 32];
#pragma unroll
        for (int o = 16; o > 0; o >>= 1) v += __shfl_xor_sync(0xffffffffu, v, o);
        if (lane == 0) rred[w] = 1.0f / v;
    }
    __syncthreads();
    float4 cs = make_float4(0.f, 0.f, 0.f, 0.f);
#pragma unroll
    for (int rr = 0; rr < RPB; rr++) {
        const float inv = rred[rr];
        float Ex = __expf(x4[rr].x * inv);
        float Ey = __expf(x4[rr].y * inv);
        float Ez = __expf(x4[rr].z * inv);
        float Ew = __expf(x4[rr].w * inv);
        uint2 o;
        o.x = enc2(Ex, Ey);
        o.y = enc2(Ez, Ew);
        *(uint2*)&g_Q[((size_t)b * NN + r0 + rr) * NN + j0] = o;
        cs.x += Ex; cs.y += Ey; cs.z += Ez; cs.w += Ew;
    }
    *(float4*)&g_part[((size_t)blockIdx.x * BB + b) * NN + j0] = cs;
}

// ===========================================================================
// Reduce colsum partials. grid (32, BB).
// ===========================================================================
__global__ __launch_bounds__(256) void k_reduce() {
    const int b = blockIdx.y, g = blockIdx.x, t = threadIdx.x;
    const int c = t & 7, p0 = t >> 3;
    const float4* P = (const float4*)g_part;
    float4 s = make_float4(0.f, 0.f, 0.f, 0.f);
#pragma unroll
    for (int p = p0; p < NBLK; p += 32) {
        float4 v = P[((size_t)p * BB + b) * (NN / 4) + g * 8 + c];
        s.x += v.x; s.y += v.y; s.z += v.z; s.w += v.w;
    }
    __shared__ float4 sm[32][8];
    sm[p0][c] = s;
    __syncthreads();
    if (t < 8) {
        float4 a = sm[0][t];
#pragma unroll
        for (int p = 1; p < 32; p++) {
            float4 v = sm[p][t];
            a.x += v.x; a.y += v.y; a.z += v.z; a.w += v.w;
        }
        *(float4*)&g_colsum[b * NN + g * 32 + t * 4] = a;
    }
}

// ===========================================================================
// Fused pair (col+row softmax) on u16 E-state.
// ===========================================================================
__global__ __launch_bounds__(256, 4) void k_fused() {
    const int b = blockIdx.y, r0 = blockIdx.x * RPB, t = threadIdx.x;
    const int j0 = t * 4;
    __shared__ float part[RPB][256];
    __shared__ float rinv[RPB];

    float4 cv = *(const float4*)&g_colsum[b * NN + j0];
    const float4 ic = make_float4(1.0f / cv.x, 1.0f / cv.y, 1.0f / cv.z, 1.0f / cv.w);

    float4 r4[RPB];
#pragma unroll
    for (int rr = 0; rr < RPB; rr++) {
        uint2 w = *(const uint2*)&g_Q[((size_t)b * NN + r0 + rr) * NN + j0];
        float4 r;
        r.x = __expf(decE(w.x & 0xFFFFu) * ic.x);
        r.y = __expf(decE(w.x >> 16) * ic.y);
        r.z = __expf(decE(w.y & 0xFFFFu) * ic.z);
        r.w = __expf(decE(w.y >> 16) * ic.w);
        r4[rr] = r;
        part[rr][t] = (r.x + r.y) + (r.z + r.w);
    }
    __syncthreads();
    {
        const int w = t >> 5, lane = t & 31;
        float v = part[w][lane];
#pragma unroll
        for (int k = 1; k < 8; k++) v += part[w][lane + k * 32];
#pragma unroll
        for (int o = 16; o > 0; o >>= 1) v += __shfl_xor_sync(0xffffffffu, v, o);
        if (lane == 0) rinv[w] = 1.0f / v;
    }
    __syncthreads();
    float4 cs = make_float4(0.f, 0.f, 0.f, 0.f);
#pragma unroll
    for (int rr = 0; rr < RPB; rr++) {
        const float ir = rinv[rr];
        float Ex = __expf(r4[rr].x * ir);
        float Ey = __expf(r4[rr].y * ir);
        float Ez = __expf(r4[rr].z * ir);
        float Ew = __expf(r4[rr].w * ir);
        uint2 o;
        o.x = enc2(Ex, Ey);
        o.y = enc2(Ez, Ew);
        *(uint2*)&g_Q[((size_t)b * NN + r0 + rr) * NN + j0] = o;
        cs.x += Ex; cs.y += Ey; cs.z += Ez; cs.w += Ew;
    }
    *(float4*)&g_part[((size_t)blockIdx.x * BB + b) * NN + j0] = cs;
}

// Last pair: col#9 + row#10; store E10 as single fp16 + partials.
__global__ __launch_bounds__(256, 4) void k_fused_last() {
    const int b = blockIdx.y, r0 = blockIdx.x * RPB, t = threadIdx.x;
    const int j0 = t * 4;
    __shared__ float part[RPB][256];
    __shared__ float rinv[RPB];

    float4 cv = *(const float4*)&g_colsum[b * NN + j0];
    const float4 ic = make_float4(1.0f / cv.x, 1.0f / cv.y, 1.0f / cv.z, 1.0f / cv.w);

    float4 r4[RPB];
#pragma unroll
    for (int rr = 0; rr < RPB; rr++) {
        uint2 w = *(const uint2*)&g_Q[((size_t)b * NN + r0 + rr) * NN + j0];
        float4 r;
        r.x = __expf(decE(w.x & 0xFFFFu) * ic.x);
        r.y = __expf(decE(w.x >> 16) * ic.y);
        r.z = __expf(decE(w.y & 0xFFFFu) * ic.z);
        r.w = __expf(decE(w.y >> 16) * ic.w);
        r4[rr] = r;
        part[rr][t] = (r.x + r.y) + (r.z + r.w);
    }
    __syncthreads();
    {
        const int w = t >> 5, lane = t & 31;
        float v = part[w][lane];
#pragma unroll
        for (int k = 1; k < 8; k++) v += part[w][lane + k * 32];
#pragma unroll
        for (int o = 16; o > 0; o >>= 1) v += __shfl_xor_sync(0xffffffffu, v, o);
        if (lane == 0) rinv[w] = 1.0f / v;
    }
    __syncthreads();
    float4 cs = make_float4(0.f, 0.f, 0.f, 0.f);
#pragma unroll
    for (int rr = 0; rr < RPB; rr++) {
        const float ir = rinv[rr];
        float Ex = __expf(r4[rr].x * ir);
        float Ey = __expf(r4[rr].y * ir);
        float Ez = __expf(r4[rr].z * ir);
        float Ew = __expf(r4[rr].w * ir);
        PackH4 H;
        H.h[0] = __float2half_rn(Ex);
        H.h[1] = __float2half_rn(Ey);
        H.h[2] = __float2half_rn(Ez);
        H.h[3] = __float2half_rn(Ew);
        *(uint2*)&g_F[((size_t)b * NN + r0 + rr) * NN + j0] = H.u;
        cs.x += Ex; cs.y += Ey; cs.z += Ez; cs.w += Ew;
    }
    *(float4*)&g_part[((size_t)blockIdx.x * BB + b) * NN + j0] = cs;
}

// ===========================================================================
// prepB: integrated final colsum reduce; B[k][f] = fp16(1024*inv_colsum*feat)
// grid (128, BB), 256 thr, 8 k-rows per block.
// ===========================================================================
__global__ __launch_bounds__(256) void k_prepB(const float* __restrict__ feat) {
    const int b = blockIdx.y, k0 = blockIdx.x * 8, t = threadIdx.x;
    __shared__ float sm[32][8];
    __shared__ float ics[8];
    {
        const int kk = t & 7, p0 = t >> 3;
        float s = 0.f;
#pragma unroll
        for (int p = p0; p < NBLK; p += 32)
            s += g_part[((size_t)p * BB + b) * NN + k0 + kk];
        sm[p0][kk] = s;
        __syncthreads();
        if (t < 8) {
            float a = 0.f;
#pragma unroll
            for (int p = 0; p < 32; p++) a += sm[p][t];
            ics[t] = 1024.0f / a;
        }
        __syncthreads();
    }
    const int k = k0 + (t >> 5);
    const int f4 = (t & 31) * 4;
    const float ic = ics[t >> 5];
    float4 v = *(const float4*)&feat[((size_t)b * NN + k) * FF + f4];
    PackH4 H;
    H.h[0] = __float2half_rn(v.x * ic);
    H.h[1] = __float2half_rn(v.y * ic);
    H.h[2] = __float2half_rn(v.z * ic);
    H.h[3] = __float2half_rn(v.w * ic);
    *(uint2*)&g_B[((size_t)b * NN + k) * FF + f4] = H.u;
}

// ===========================================================================
// fp16 single-product HMMA GEMM: out = 2^-10 * F @ B
// 128x128 tile, K-chunks of 32, cp.async double buffer.
// Buffers: A 128 rows x 64B (pad 80) = 10240; B 32 rows x 256B (pad 272) = 8704
// ===========================================================================
#define SBUF 18944
#define BOFF 10240

__global__ __launch_bounds__(256, 2) void k_gemm(float* __restrict__ out) {
    extern __shared__ char smem[];
    const int b = blockIdx.y, i0 = blockIdx.x * 128, t = threadIdx.x;
    const int wid = t >> 5, lane = t & 31;
    const int wm = wid & 3, wn = wid >> 2;
    const uint32_t sb = smem_u32(smem);

    const int rowA = t >> 1, halfA = (t & 1) * 32;
    const int rowB = t >> 3, pB = (t & 7) * 32;
    const char* srcA = (const char*)(g_F + ((size_t)b * NN + i0 + rowA) * NN) + halfA;
    const char* srcB = (const char*)(g_B + (size_t)b * NN * FF) + rowB * 256 + pB;
    const uint32_t dA = sb + rowA * 80 + halfA;
    const uint32_t dB = sb + BOFF + rowB * 272 + pB;

#define ISSUE_CHUNK(cc)  do {                                            \
        const int _s = (cc) & 1;                                         \
        const size_t _ao = (size_t)(cc) * CK * 2;                        \
        CP16(dA + _s * SBUF,      srcA + _ao);                           \
        CP16(dA + _s * SBUF + 16, srcA + _ao + 16);                      \
        const size_t _bo = (size_t)(cc) * CK * 256;                      \
        CP16(dB + _s * SBUF,      srcB + _bo);                           \
        CP16(dB + _s * SBUF + 16, srcB + _bo + 16);                      \
        CP_COMMIT();                                                     \
    } while (0)

    float acc[2][8][4];
#pragma unroll
    for (int mf = 0; mf < 2; mf++)
#pragma unroll
        for (int nf = 0; nf < 8; nf++)
#pragma unroll
            for (int q = 0; q < 4; q++) acc[mf][nf][q] = 0.f;

    ISSUE_CHUNK(0);

    for (int c = 0; c < GC; ++c) {
        if (c < GC - 1) { ISSUE_CHUNK(c + 1); CP_WAIT1(); }
        else            { CP_WAIT0(); }
        __syncthreads();

        const uint32_t buf = sb + (c & 1) * SBUF;
#pragma unroll
        for (int ks = 0; ks < 2; ks++) {
            uint32_t aF[2][4];
#pragma unroll
            for (int mf = 0; mf < 2; mf++) {
                const int r0 = wm * 32 + mf * 16;
                ldsm_x4(aF[mf], buf + (r0 + (lane & 15)) * 80 + ks * 32 + (lane >> 4) * 16);
            }
            uint32_t bF[4][4];
#pragma unroll
            for (int ng = 0; ng < 4; ng++) {
                const int n0 = wn * 64 + ng * 16;
                ldsm_x4_t(bF[ng], buf + BOFF + (ks * 16 + (lane & 15)) * 272 + n0 * 2 + (lane >> 4) * 16);
            }
#pragma unroll
            for (int mf = 0; mf < 2; mf++)
#pragma unroll
                for (int ng = 0; ng < 4; ng++)
#pragma unroll
                    for (int h = 0; h < 2; h++)
                        mma_f16(acc[mf][ng * 2 + h], aF[mf], &bF[ng][h * 2]);
        }
        __syncthreads();
    }

    const int gid = lane >> 2, t4 = lane & 3;
    const float sc = 0.0009765625f;   // 2^-10
#pragma unroll
    for (int mf = 0; mf < 2; mf++) {
        const int row = i0 + wm * 32 + mf * 16 + gid;
#pragma unroll
        for (int nf = 0; nf < 8; nf++) {
            const int col = wn * 64 + nf * 8 + t4 * 2;
            const float* d = acc[mf][nf];
            *(float2*)&out[((size_t)b * NN + row) * FF + col]     = make_float2(d[0] * sc, d[1] * sc);
            *(float2*)&out[((size_t)b * NN + row + 8) * FF + col] = make_float2(d[2] * sc, d[3] * sc);
        }
    }
}

// ===========================================================================
extern "C" void kernel_launch(void* const* d_in, const int* in_sizes, int n_in,
                              void* d_out, int out_size) {
    const float* feat = (const float*)d_in[0];   // [B,N,F]
    const float* tmpl = (const float*)d_in[1];   // [1,N,N]
    const float* uni  = (const float*)d_in[2];   // [B,N,N]
    float* out = (float*)d_out;                  // [B,N,F]

    cudaFuncSetAttribute(k_gemm, cudaFuncAttributeMaxDynamicSharedMemorySize, 2 * SBUF);

    k_init<<<dim3(NBLK, BB), 256>>>(tmpl, uni);
    k_reduce<<<dim3(32, BB), 256>>>();
    for (int it = 0; it < 8; ++it) {
        k_fused<<<dim3(NBLK, BB), 256>>>();
        k_reduce<<<dim3(32, BB), 256>>>();
    }
    k_fused_last<<<dim3(NBLK, BB), 256>>>();
    k_prepB<<<dim3(NBLK, BB), 256>>>(feat);
    k_gemm<<<dim3(8, BB), 256, 2 * SBUF>>>(out);
}